// round 5
// baseline (speedup 1.0000x reference)
#include <cuda_runtime.h>

// ---------------------------------------------------------------------------
// Problem constants: B=4, E=400000, N_NODES=50000, N_REL=500, D=64, D_LG=256,
// K_PER_VI=20, N_MEM=131072. Scratch via device globals (no allocation).
// ---------------------------------------------------------------------------
__device__ float g_hc[131072 * 64];   // tanh(hidden_con @ Wc + bc)
__device__ float g_hu[50000 * 64];    // tanh(hidden_uncon @ Wu + bu)

// ---------------- packed f32x2 helpers (sm_103a) ----------------
__device__ __forceinline__ void unpack2(unsigned long long u, float& x, float& y) {
    asm("mov.b64 {%0,%1}, %2;" : "=f"(x), "=f"(y) : "l"(u));
}
__device__ __forceinline__ void fma2(unsigned long long& d,
                                     unsigned long long a, unsigned long long b) {
    asm("fma.rn.f32x2 %0, %1, %2, %0;" : "+l"(d) : "l"(a), "l"(b));
}

__device__ __forceinline__ float tanh_fast(float x) {
    float e = __expf(-2.0f * fabsf(x));
    float t = (1.0f - e) / (1.0f + e);
    return copysignf(t, x);
}

// ---------------------------------------------------------------------------
// Fused projection kernel: out[row,0:64] = tanh(X[row,0:K] @ W[K,64] + bias)
// for BOTH tables in one launch (block range split).
// Tile: block = 128 rows x 64 cols, 256 threads = 8 warps.
// Thread tile = 2 rows x 16 cols (16 u64 f32x2 accs).
// X staged transposed+duplicated (XsT[k][2r]=(x,x)); per-kk x fetch is one
// LDS.128 giving both rows. W staged [32][64], 4 broadcast LDS.128 per kk
// (split into 2 live ulonglong2 groups to cap register pressure).
// __launch_bounds__(256,4): 4 blocks/SM (32 warps) to hide LDS/barrier latency.
// ---------------------------------------------------------------------------
__global__ void __launch_bounds__(256, 4) proj_both_kernel(
    const float* __restrict__ Xc, const float* __restrict__ Wc,
    const float* __restrict__ bc, int rows_c, int nb_c,
    const float* __restrict__ Xu, const float* __restrict__ Wu,
    const float* __restrict__ bu, int rows_u)
{
    extern __shared__ float sm[];
    float* XsT = sm;            // chunk [32][260]; epilogue reuse [128][68]
    float* Ws  = sm + 8704;     // [32][64]

    const float *X, *W, *bias;
    float* out;
    int rows, K, bid;
    if ((int)blockIdx.x < nb_c) {
        X = Xc; W = Wc; bias = bc; out = g_hc; rows = rows_c; K = 64;
        bid = blockIdx.x;
    } else {
        X = Xu; W = Wu; bias = bu; out = g_hu; rows = rows_u; K = 256;
        bid = blockIdx.x - nb_c;
    }

    const int tid  = threadIdx.x;
    const int lane = tid & 31;
    const int warp = tid >> 5;
    const int cg   = lane >> 3;             // 0..3: 16-col group
    const int rp   = lane & 7;              // row-pair index
    const int r0   = bid * 128;
    const int row_base = warp * 16 + 2 * rp;   // rows row_base, row_base+1

    unsigned long long acc[2][8];
#pragma unroll
    for (int r = 0; r < 2; r++)
#pragma unroll
        for (int j = 0; j < 8; j++) acc[r][j] = 0ull;

    for (int k0 = 0; k0 < K; k0 += 32) {
        __syncthreads();
        // ---- stage X chunk: 128 rows x 32 k, transposed + duplicated ----
#pragma unroll
        for (int i = 0; i < 4; i++) {
            int idx = tid + i * 256;        // 0..1023 float4s
            int row = idx >> 3, k4 = idx & 7;
            float4 v = make_float4(0.f, 0.f, 0.f, 0.f);
            if (r0 + row < rows)
                v = *reinterpret_cast<const float4*>(
                        &X[(size_t)(r0 + row) * K + k0 + 4 * k4]);
            float* p = &XsT[(4 * k4) * 260 + 2 * row];
            *reinterpret_cast<float2*>(p)       = make_float2(v.x, v.x);
            *reinterpret_cast<float2*>(p + 260) = make_float2(v.y, v.y);
            *reinterpret_cast<float2*>(p + 520) = make_float2(v.z, v.z);
            *reinterpret_cast<float2*>(p + 780) = make_float2(v.w, v.w);
        }
        // ---- stage W chunk: 32 x 64 ----
#pragma unroll
        for (int i = 0; i < 2; i++) {
            int idx = tid + i * 256;        // 0..511 float4s
            *reinterpret_cast<float4*>(&Ws[4 * idx]) =
                *reinterpret_cast<const float4*>(&W[(size_t)k0 * 64 + 4 * idx]);
        }
        __syncthreads();

        const float* xb = &XsT[2 * row_base];
        const float* wb = &Ws[cg * 16];
#pragma unroll 4
        for (int kk = 0; kk < 32; kk++) {
            ulonglong2 xq =
                *reinterpret_cast<const ulonglong2*>(xb + (size_t)kk * 260);
            const ulonglong2* wp =
                reinterpret_cast<const ulonglong2*>(wb + (size_t)kk * 64);
            {
                ulonglong2 wA = wp[0], wB = wp[1];
                fma2(acc[0][0], xq.x, wA.x); fma2(acc[0][1], xq.x, wA.y);
                fma2(acc[0][2], xq.x, wB.x); fma2(acc[0][3], xq.x, wB.y);
                fma2(acc[1][0], xq.y, wA.x); fma2(acc[1][1], xq.y, wA.y);
                fma2(acc[1][2], xq.y, wB.x); fma2(acc[1][3], xq.y, wB.y);
            }
            {
                ulonglong2 wC = wp[2], wD = wp[3];
                fma2(acc[0][4], xq.x, wC.x); fma2(acc[0][5], xq.x, wC.y);
                fma2(acc[0][6], xq.x, wD.x); fma2(acc[0][7], xq.x, wD.y);
                fma2(acc[1][4], xq.y, wC.x); fma2(acc[1][5], xq.y, wC.y);
                fma2(acc[1][6], xq.y, wD.x); fma2(acc[1][7], xq.y, wD.y);
            }
        }
    }

    // ---- epilogue: bias + tanh, stage to smem [128][68], coalesced stores --
    __syncthreads();
    float bv[16];
#pragma unroll
    for (int j = 0; j < 16; j++) bv[j] = __ldg(&bias[cg * 16 + j]);
#pragma unroll
    for (int r = 0; r < 2; r++) {
        float* dst = &XsT[(size_t)(row_base + r) * 68 + cg * 16];
#pragma unroll
        for (int j = 0; j < 8; j++) {
            float a, b;
            unpack2(acc[r][j], a, b);
            *reinterpret_cast<float2*>(dst + 2 * j) =
                make_float2(tanh_fast(a + bv[2 * j]), tanh_fast(b + bv[2 * j + 1]));
        }
    }
    __syncthreads();
#pragma unroll
    for (int i = 0; i < 8; i++) {
        int idx = tid + i * 256;            // 0..2047 float4s
        int row = idx >> 4, c4 = idx & 15;
        if (r0 + row < rows)
            *reinterpret_cast<float4*>(&out[(size_t)(r0 + row) * 64 + 4 * c4]) =
                *reinterpret_cast<const float4*>(&XsT[(size_t)row * 68 + 4 * c4]);
    }
}

// ---------------------------------------------------------------------------
// Edge kernel v3: one segment per 320-thread block (10 warps, 2 edges/warp).
// No weight smem staging: weight rows come via __ldg (same address across all
// warps -> L1-resident), removing one barrier. out_b is dropped: it adds the
// same constant to every logit in a segment, so softmax is invariant to it.
// Gathers (8 float2/warp) are front-batched; occupancy target 4 blocks/SM.
// ---------------------------------------------------------------------------
__global__ void __launch_bounds__(320, 4) edge_kernel(
    const float* __restrict__ natt, const int* __restrict__ edges,
    const float* __restrict__ edges_y, const float* __restrict__ rel_table,
    const float* __restrict__ ws, const float* __restrict__ fb,
    const float* __restrict__ out_w,
    float* __restrict__ out, int n_nodes)
{
    __shared__ float s_logit[20];

    const int tid  = threadIdx.x;
    const int wid  = tid >> 5;             // 0..9
    const int lane = tid & 31;

    const long long e_base = (long long)blockIdx.x * 20 + wid * 2;

    // lanes 0..3 load the 4 int4 of this warp's 2 edges (coalesced)
    int4 a = make_int4(0, 0, 0, 0);
    if (lane < 4)
        a = __ldg(&reinterpret_cast<const int4*>(edges)[2 * e_base + lane]);

    // edge e: ra at lane 2e, rb at lane 2e+1
    const int vj0   = __shfl_sync(0xFFFFFFFFu, a.z, 0);
    const int rel0  = __shfl_sync(0xFFFFFFFFu, a.w, 0);
    const int e2vi0 = __shfl_sync(0xFFFFFFFFu, a.z, 1);
    const int e2vj0 = __shfl_sync(0xFFFFFFFFu, a.w, 1);
    const int vj1   = __shfl_sync(0xFFFFFFFFu, a.z, 2);
    const int rel1  = __shfl_sync(0xFFFFFFFFu, a.w, 2);
    const int e2vi1 = __shfl_sync(0xFFFFFFFFu, a.z, 3);
    const int e2vj1 = __shfl_sync(0xFFFFFFFFu, a.w, 3);
    const int eg    = __shfl_sync(0xFFFFFFFFu, a.x, 0);
    const int vi    = __shfl_sync(0xFFFFFFFFu, a.y, 0);
    const int vjL   = __shfl_sync(0xFFFFFFFFu, a.z, 2 * (lane & 1));

    // front-batched independent gathers (MLP 9) + scalars
    const int d = 2 * lane;
    const float2 f0a = __ldg(reinterpret_cast<const float2*>(&g_hc[(size_t)e2vi0 * 64 + d]));
    const float2 f0b = __ldg(reinterpret_cast<const float2*>(&g_hc[(size_t)e2vi1 * 64 + d]));
    const float2 f3a = __ldg(reinterpret_cast<const float2*>(&g_hc[(size_t)e2vj0 * 64 + d]));
    const float2 f3b = __ldg(reinterpret_cast<const float2*>(&g_hc[(size_t)e2vj1 * 64 + d]));
    const float2 f4a = __ldg(reinterpret_cast<const float2*>(&g_hu[(size_t)vj0 * 64 + d]));
    const float2 f4b = __ldg(reinterpret_cast<const float2*>(&g_hu[(size_t)vj1 * 64 + d]));
    const float2 f2a = __ldg(reinterpret_cast<const float2*>(&rel_table[(size_t)rel0 * 64 + d]));
    const float2 f2b = __ldg(reinterpret_cast<const float2*>(&rel_table[(size_t)rel1 * 64 + d]));
    const float2 f1  = __ldg(reinterpret_cast<const float2*>(&g_hu[(size_t)vi * 64 + d]));
    const float att  = __ldg(&natt[(size_t)eg * n_nodes + vi]);
    const float ey   = (lane < 2) ? __ldg(&edges_y[e_base + lane]) : 0.0f;

    // weight rows: uniform addresses across warps -> L1-resident
    const float2 w0 = __ldg(reinterpret_cast<const float2*>(&ws[0 * 64 + d]));
    const float2 w1 = __ldg(reinterpret_cast<const float2*>(&ws[1 * 64 + d]));
    const float2 w2 = __ldg(reinterpret_cast<const float2*>(&ws[2 * 64 + d]));
    const float2 w3 = __ldg(reinterpret_cast<const float2*>(&ws[3 * 64 + d]));
    const float2 w4 = __ldg(reinterpret_cast<const float2*>(&ws[4 * 64 + d]));
    const float2 w5 = __ldg(reinterpret_cast<const float2*>(&ws[5 * 64 + d]));
    const float2 w6 = __ldg(reinterpret_cast<const float2*>(&ws[6 * 64 + d]));
    const float2 w7 = __ldg(reinterpret_cast<const float2*>(&ws[7 * 64 + d]));
    const float2 vb = __ldg(reinterpret_cast<const float2*>(&fb[d]));
    const float2 ow = __ldg(reinterpret_cast<const float2*>(&out_w[d]));

    // f1-dependent terms shared by both edges:
    //   c3 = f0*w0 + (f0*f2)*w1 + f1*w4 + (f1*f2)*w5   (coeff of f3)
    //   c4 = f0*w2 + (f0*f2)*w3 + f1*w6 + (f1*f2)*w7   (coeff of f4)
    const float h4x = f1.x * w4.x, h4y = f1.y * w4.y;
    const float h5x = f1.x * w5.x, h5y = f1.y * w5.y;
    const float h6x = f1.x * w6.x, h6y = f1.y * w6.y;
    const float h7x = f1.x * w7.x, h7y = f1.y * w7.y;

#define EDGE_LOGIT(f0v, f2v, f3v, f4v, lout)                                     \
    {                                                                            \
        float a1x = f0v.x * f2v.x, a1y = f0v.y * f2v.y;                          \
        float c3x = fmaf(f0v.x, w0.x, fmaf(a1x, w1.x, fmaf(f2v.x, h5x, h4x)));   \
        float c3y = fmaf(f0v.y, w0.y, fmaf(a1y, w1.y, fmaf(f2v.y, h5y, h4y)));   \
        float c4x = fmaf(f0v.x, w2.x, fmaf(a1x, w3.x, fmaf(f2v.x, h7x, h6x)));   \
        float c4y = fmaf(f0v.y, w2.y, fmaf(a1y, w3.y, fmaf(f2v.y, h7y, h6y)));   \
        float oxv = fmaf(f3v.x, c3x, fmaf(f4v.x, c4x, vb.x));                    \
        float oyv = fmaf(f3v.y, c3y, fmaf(f4v.y, c4y, vb.y));                    \
        lout = fmaf(fmaxf(oxv, 0.0f), ow.x, fmaxf(oyv, 0.0f) * ow.y);            \
    }

    float l0, l1;
    EDGE_LOGIT(f0a, f2a, f3a, f4a, l0)
    EDGE_LOGIT(f0b, f2b, f3b, f4b, l1)
#undef EDGE_LOGIT

#pragma unroll
    for (int s = 16; s > 0; s >>= 1) {
        l0 += __shfl_xor_sync(0xFFFFFFFFu, l0, s);
        l1 += __shfl_xor_sync(0xFFFFFFFFu, l1, s);
    }
    if (lane == 0) {
        s_logit[2 * wid]     = l0;
        s_logit[2 * wid + 1] = l1;
    }
    __syncthreads();

    // segment softmax (each warp redundantly)
    float l = (lane < 20) ? s_logit[lane] : -1e30f;
    float m = l;
#pragma unroll
    for (int s = 16; s > 0; s >>= 1) m = fmaxf(m, __shfl_xor_sync(0xFFFFFFFFu, m, s));
    float ev = (lane < 20) ? __expf(l - m) : 0.0f;
#pragma unroll
    for (int s = 16; s > 0; s >>= 1) ev += __shfl_xor_sync(0xFFFFFFFFu, ev, s);

    if (lane < 2) {
        float lg = s_logit[2 * wid + lane];
        float trans = __expf(lg - m) / ev;
        atomicAdd(&out[(size_t)eg * n_nodes + vjL], trans * att * ey);
    }
}

// ---------------------------------------------------------------------------
extern "C" void kernel_launch(void* const* d_in, const int* in_sizes, int n_in,
                              void* d_out, int out_size)
{
    const float* natt    = (const float*)d_in[0];
    const int*   edges   = (const int*)d_in[1];
    const float* edges_y = (const float*)d_in[2];
    const float* hu_in   = (const float*)d_in[3];   // [1, n_nodes, 256]
    const float* hc_in   = (const float*)d_in[4];   // [n_mem, 64]
    const float* Wc      = (const float*)d_in[5];
    const float* bc      = (const float*)d_in[6];
    const float* Wu      = (const float*)d_in[7];
    const float* bu      = (const float*)d_in[8];
    const float* rel_t   = (const float*)d_in[9];
    const float* ws      = (const float*)d_in[10];
    const float* fb      = (const float*)d_in[11];
    const float* ow      = (const float*)d_in[12];

    const int E       = in_sizes[2];
    const int n_nodes = in_sizes[3] / 256;
    const int n_mem   = in_sizes[4] / 64;
    const int n_seg   = E / 20;

    const int nb_c = (n_mem + 127) / 128;      // 1024
    const int nb_u = (n_nodes + 127) / 128;    // 391

    const int dyn_smem = (8704 + 2048) * 4;    // 43008 bytes
    cudaFuncSetAttribute(proj_both_kernel,
                         cudaFuncAttributeMaxDynamicSharedMemorySize, dyn_smem);
    cudaFuncSetAttribute(proj_both_kernel,
                         cudaFuncAttributePreferredSharedMemoryCarveout, 100);

    cudaMemsetAsync(d_out, 0, (size_t)out_size * sizeof(float));

    proj_both_kernel<<<nb_c + nb_u, 256, dyn_smem>>>(
        hc_in, Wc, bc, n_mem, nb_c, hu_in, Wu, bu, n_nodes);

    edge_kernel<<<n_seg, 320>>>(natt, edges, edges_y, rel_t, ws, fb, ow,
                                (float*)d_out, n_nodes);
}

// round 6
// speedup vs baseline: 1.2412x; 1.2412x over previous
#include <cuda_runtime.h>

// ---------------------------------------------------------------------------
// Problem constants: B=4, E=400000, N_NODES=50000, N_REL=500, D=64, D_LG=256,
// K_PER_VI=20, N_MEM=131072. Scratch via device globals (no allocation).
// ---------------------------------------------------------------------------
__device__ float g_hc[131072 * 64];   // tanh(hidden_con @ Wc + bc)
__device__ float g_hu[50000 * 64];    // tanh(hidden_uncon @ Wu + bu)

// ---------------- packed f32x2 helpers (sm_103a) ----------------
__device__ __forceinline__ void unpack2(unsigned long long u, float& x, float& y) {
    asm("mov.b64 {%0,%1}, %2;" : "=f"(x), "=f"(y) : "l"(u));
}
__device__ __forceinline__ void fma2(unsigned long long& d,
                                     unsigned long long a, unsigned long long b) {
    asm("fma.rn.f32x2 %0, %1, %2, %0;" : "+l"(d) : "l"(a), "l"(b));
}

__device__ __forceinline__ float tanh_fast(float x) {
    float e = __expf(-2.0f * fabsf(x));
    float t = (1.0f - e) / (1.0f + e);
    return copysignf(t, x);
}

// ---------------------------------------------------------------------------
// Fused projection kernel (round-4 config: 3 blocks/SM, natural ~75 regs).
// out[row,0:64] = tanh(X[row,0:K] @ W[K,64] + bias) for BOTH tables.
// Block = 128 rows x 64 cols, 256 threads; thread tile 2 rows x 16 cols.
// ---------------------------------------------------------------------------
__global__ void __launch_bounds__(256, 3) proj_both_kernel(
    const float* __restrict__ Xc, const float* __restrict__ Wc,
    const float* __restrict__ bc, int rows_c, int nb_c,
    const float* __restrict__ Xu, const float* __restrict__ Wu,
    const float* __restrict__ bu, int rows_u)
{
    extern __shared__ float sm[];
    float* XsT = sm;            // chunk [32][260]; epilogue reuse [128][68]
    float* Ws  = sm + 8704;     // [32][64]

    const float *X, *W, *bias;
    float* out;
    int rows, K, bid;
    if ((int)blockIdx.x < nb_c) {
        X = Xc; W = Wc; bias = bc; out = g_hc; rows = rows_c; K = 64;
        bid = blockIdx.x;
    } else {
        X = Xu; W = Wu; bias = bu; out = g_hu; rows = rows_u; K = 256;
        bid = blockIdx.x - nb_c;
    }

    const int tid  = threadIdx.x;
    const int lane = tid & 31;
    const int warp = tid >> 5;
    const int cg   = lane >> 3;             // 0..3: 16-col group
    const int rp   = lane & 7;              // row-pair index
    const int r0   = bid * 128;
    const int row_base = warp * 16 + 2 * rp;

    unsigned long long acc[2][8];
#pragma unroll
    for (int r = 0; r < 2; r++)
#pragma unroll
        for (int j = 0; j < 8; j++) acc[r][j] = 0ull;

    for (int k0 = 0; k0 < K; k0 += 32) {
        __syncthreads();
        // ---- stage X chunk: 128 rows x 32 k, transposed + duplicated ----
#pragma unroll
        for (int i = 0; i < 4; i++) {
            int idx = tid + i * 256;        // 0..1023 float4s
            int row = idx >> 3, k4 = idx & 7;
            float4 v = make_float4(0.f, 0.f, 0.f, 0.f);
            if (r0 + row < rows)
                v = *reinterpret_cast<const float4*>(
                        &X[(size_t)(r0 + row) * K + k0 + 4 * k4]);
            float* p = &XsT[(4 * k4) * 260 + 2 * row];
            *reinterpret_cast<float2*>(p)       = make_float2(v.x, v.x);
            *reinterpret_cast<float2*>(p + 260) = make_float2(v.y, v.y);
            *reinterpret_cast<float2*>(p + 520) = make_float2(v.z, v.z);
            *reinterpret_cast<float2*>(p + 780) = make_float2(v.w, v.w);
        }
        // ---- stage W chunk: 32 x 64 ----
#pragma unroll
        for (int i = 0; i < 2; i++) {
            int idx = tid + i * 256;        // 0..511 float4s
            *reinterpret_cast<float4*>(&Ws[4 * idx]) =
                *reinterpret_cast<const float4*>(&W[(size_t)k0 * 64 + 4 * idx]);
        }
        __syncthreads();

        const float* xb = &XsT[2 * row_base];
        const float* wb = &Ws[cg * 16];
#pragma unroll 8
        for (int kk = 0; kk < 32; kk++) {
            ulonglong2 xq =
                *reinterpret_cast<const ulonglong2*>(xb + (size_t)kk * 260);
            const ulonglong2* wp =
                reinterpret_cast<const ulonglong2*>(wb + (size_t)kk * 64);
            ulonglong2 wA = wp[0], wB = wp[1], wC = wp[2], wD = wp[3];
            unsigned long long wv[8] = {wA.x, wA.y, wB.x, wB.y,
                                        wC.x, wC.y, wD.x, wD.y};
#pragma unroll
            for (int j = 0; j < 8; j++) fma2(acc[0][j], xq.x, wv[j]);
#pragma unroll
            for (int j = 0; j < 8; j++) fma2(acc[1][j], xq.y, wv[j]);
        }
    }

    // ---- epilogue: bias + tanh, stage to smem [128][68], coalesced stores --
    __syncthreads();
    float bv[16];
#pragma unroll
    for (int j = 0; j < 16; j++) bv[j] = __ldg(&bias[cg * 16 + j]);
#pragma unroll
    for (int r = 0; r < 2; r++) {
        float* dst = &XsT[(size_t)(row_base + r) * 68 + cg * 16];
#pragma unroll
        for (int j = 0; j < 8; j++) {
            float a, b;
            unpack2(acc[r][j], a, b);
            *reinterpret_cast<float2*>(dst + 2 * j) =
                make_float2(tanh_fast(a + bv[2 * j]), tanh_fast(b + bv[2 * j + 1]));
        }
    }
    __syncthreads();
#pragma unroll
    for (int i = 0; i < 8; i++) {
        int idx = tid + i * 256;            // 0..2047 float4s
        int row = idx >> 4, c4 = idx & 15;
        if (r0 + row < rows)
            *reinterpret_cast<float4*>(&out[(size_t)(r0 + row) * 64 + 4 * c4]) =
                *reinterpret_cast<const float4*>(&XsT[(size_t)row * 68 + 4 * c4]);
    }
}

// ---------------------------------------------------------------------------
// Edge kernel v4: 2 segments per 320-thread block (10 warps), 5 warps/segment,
// 4 edges/warp. Weights staged in smem once per block (amortized LDS instead
// of per-warp LDG reloads); gathers front-batched before the single barrier.
// out_b dropped (softmax-invariant constant). Target 3 blocks/SM (30 warps).
// ---------------------------------------------------------------------------
__global__ void __launch_bounds__(320, 3) edge_kernel(
    const float* __restrict__ natt, const int* __restrict__ edges,
    const float* __restrict__ edges_y, const float* __restrict__ rel_table,
    const float* __restrict__ ws, const float* __restrict__ fb,
    const float* __restrict__ out_w,
    float* __restrict__ out, int n_nodes)
{
    __shared__ __align__(16) float s_w[640];   // ws[512] | fb[64] | ow[64]
    __shared__ float s_logit[2][20];

    const int tid   = threadIdx.x;
    const int wid   = tid >> 5;            // 0..9
    const int lane  = tid & 31;
    const int seg_l = wid / 5;             // 0..1
    const int wis   = wid - seg_l * 5;     // 0..4

    const long long e_base = (long long)blockIdx.x * 40 + seg_l * 20 + wis * 4;

    // lanes 0..7 load the 8 int4 of this warp's 4 edges (coalesced 128B)
    int4 a = make_int4(0, 0, 0, 0);
    if (lane < 8)
        a = __ldg(&reinterpret_cast<const int4*>(edges)[2 * e_base + lane]);

    // edge k: ra at lane 2k, rb at lane 2k+1
    const int eg    = __shfl_sync(0xFFFFFFFFu, a.x, 0);
    const int vi    = __shfl_sync(0xFFFFFFFFu, a.y, 0);
    const int vj0   = __shfl_sync(0xFFFFFFFFu, a.z, 0);
    const int rel0  = __shfl_sync(0xFFFFFFFFu, a.w, 0);
    const int e2vi0 = __shfl_sync(0xFFFFFFFFu, a.z, 1);
    const int e2vj0 = __shfl_sync(0xFFFFFFFFu, a.w, 1);
    const int vj1   = __shfl_sync(0xFFFFFFFFu, a.z, 2);
    const int rel1  = __shfl_sync(0xFFFFFFFFu, a.w, 2);
    const int e2vi1 = __shfl_sync(0xFFFFFFFFu, a.z, 3);
    const int e2vj1 = __shfl_sync(0xFFFFFFFFu, a.w, 3);
    const int vj2   = __shfl_sync(0xFFFFFFFFu, a.z, 4);
    const int rel2  = __shfl_sync(0xFFFFFFFFu, a.w, 4);
    const int e2vi2 = __shfl_sync(0xFFFFFFFFu, a.z, 5);
    const int e2vj2 = __shfl_sync(0xFFFFFFFFu, a.w, 5);
    const int vj3   = __shfl_sync(0xFFFFFFFFu, a.z, 6);
    const int rel3  = __shfl_sync(0xFFFFFFFFu, a.w, 6);
    const int e2vi3 = __shfl_sync(0xFFFFFFFFu, a.z, 7);
    const int e2vj3 = __shfl_sync(0xFFFFFFFFu, a.w, 7);
    const int vjL   = __shfl_sync(0xFFFFFFFFu, a.z, 2 * (lane & 3));

    // stage weights once per block (640 floats over 320 threads)
    {
        int i = tid;
        s_w[i] = (i < 512) ? __ldg(&ws[i])
                           : (i < 576 ? __ldg(&fb[i - 512]) : __ldg(&out_w[i - 576]));
        int i2 = tid + 320;
        s_w[i2] = (i2 < 512) ? __ldg(&ws[i2])
                             : (i2 < 576 ? __ldg(&fb[i2 - 512]) : __ldg(&out_w[i2 - 576]));
    }

    // front-batched independent gathers (17 float2 + scalars, MLP high)
    const int d = 2 * lane;
    const float2 f0a = __ldg(reinterpret_cast<const float2*>(&g_hc[(size_t)e2vi0 * 64 + d]));
    const float2 f0b = __ldg(reinterpret_cast<const float2*>(&g_hc[(size_t)e2vi1 * 64 + d]));
    const float2 f0c = __ldg(reinterpret_cast<const float2*>(&g_hc[(size_t)e2vi2 * 64 + d]));
    const float2 f0d = __ldg(reinterpret_cast<const float2*>(&g_hc[(size_t)e2vi3 * 64 + d]));
    const float2 f3a = __ldg(reinterpret_cast<const float2*>(&g_hc[(size_t)e2vj0 * 64 + d]));
    const float2 f3b = __ldg(reinterpret_cast<const float2*>(&g_hc[(size_t)e2vj1 * 64 + d]));
    const float2 f3c = __ldg(reinterpret_cast<const float2*>(&g_hc[(size_t)e2vj2 * 64 + d]));
    const float2 f3d = __ldg(reinterpret_cast<const float2*>(&g_hc[(size_t)e2vj3 * 64 + d]));
    const float2 f4a = __ldg(reinterpret_cast<const float2*>(&g_hu[(size_t)vj0 * 64 + d]));
    const float2 f4b = __ldg(reinterpret_cast<const float2*>(&g_hu[(size_t)vj1 * 64 + d]));
    const float2 f4c = __ldg(reinterpret_cast<const float2*>(&g_hu[(size_t)vj2 * 64 + d]));
    const float2 f4d = __ldg(reinterpret_cast<const float2*>(&g_hu[(size_t)vj3 * 64 + d]));
    const float2 f2a = __ldg(reinterpret_cast<const float2*>(&rel_table[(size_t)rel0 * 64 + d]));
    const float2 f2b = __ldg(reinterpret_cast<const float2*>(&rel_table[(size_t)rel1 * 64 + d]));
    const float2 f2c = __ldg(reinterpret_cast<const float2*>(&rel_table[(size_t)rel2 * 64 + d]));
    const float2 f2d = __ldg(reinterpret_cast<const float2*>(&rel_table[(size_t)rel3 * 64 + d]));
    const float2 f1  = __ldg(reinterpret_cast<const float2*>(&g_hu[(size_t)vi * 64 + d]));
    const float att  = __ldg(&natt[(size_t)eg * n_nodes + vi]);
    const float ey   = (lane < 4) ? __ldg(&edges_y[e_base + lane]) : 0.0f;

    __syncthreads();   // weights staged

    const float2 w0 = *reinterpret_cast<const float2*>(&s_w[0 * 64 + d]);
    const float2 w1 = *reinterpret_cast<const float2*>(&s_w[1 * 64 + d]);
    const float2 w2 = *reinterpret_cast<const float2*>(&s_w[2 * 64 + d]);
    const float2 w3 = *reinterpret_cast<const float2*>(&s_w[3 * 64 + d]);
    const float2 w4 = *reinterpret_cast<const float2*>(&s_w[4 * 64 + d]);
    const float2 w5 = *reinterpret_cast<const float2*>(&s_w[5 * 64 + d]);
    const float2 w6 = *reinterpret_cast<const float2*>(&s_w[6 * 64 + d]);
    const float2 w7 = *reinterpret_cast<const float2*>(&s_w[7 * 64 + d]);
    const float2 vb = *reinterpret_cast<const float2*>(&s_w[512 + d]);
    const float2 ow = *reinterpret_cast<const float2*>(&s_w[576 + d]);

    // f1-dependent terms shared by all 4 edges:
    //   c3 = f0*w0 + (f0*f2)*w1 + f1*w4 + (f1*f2)*w5   (coeff of f3)
    //   c4 = f0*w2 + (f0*f2)*w3 + f1*w6 + (f1*f2)*w7   (coeff of f4)
    const float h4x = f1.x * w4.x, h4y = f1.y * w4.y;
    const float h5x = f1.x * w5.x, h5y = f1.y * w5.y;
    const float h6x = f1.x * w6.x, h6y = f1.y * w6.y;
    const float h7x = f1.x * w7.x, h7y = f1.y * w7.y;

#define EDGE_LOGIT(f0v, f2v, f3v, f4v, lout)                                     \
    {                                                                            \
        float a1x = f0v.x * f2v.x, a1y = f0v.y * f2v.y;                          \
        float c3x = fmaf(f0v.x, w0.x, fmaf(a1x, w1.x, fmaf(f2v.x, h5x, h4x)));   \
        float c3y = fmaf(f0v.y, w0.y, fmaf(a1y, w1.y, fmaf(f2v.y, h5y, h4y)));   \
        float c4x = fmaf(f0v.x, w2.x, fmaf(a1x, w3.x, fmaf(f2v.x, h7x, h6x)));   \
        float c4y = fmaf(f0v.y, w2.y, fmaf(a1y, w3.y, fmaf(f2v.y, h7y, h6y)));   \
        float oxv = fmaf(f3v.x, c3x, fmaf(f4v.x, c4x, vb.x));                    \
        float oyv = fmaf(f3v.y, c3y, fmaf(f4v.y, c4y, vb.y));                    \
        lout = fmaf(fmaxf(oxv, 0.0f), ow.x, fmaxf(oyv, 0.0f) * ow.y);            \
    }

    float l0, l1, l2, l3;
    EDGE_LOGIT(f0a, f2a, f3a, f4a, l0)
    EDGE_LOGIT(f0b, f2b, f3b, f4b, l1)
    EDGE_LOGIT(f0c, f2c, f3c, f4c, l2)
    EDGE_LOGIT(f0d, f2d, f3d, f4d, l3)
#undef EDGE_LOGIT

#pragma unroll
    for (int s = 16; s > 0; s >>= 1) {
        l0 += __shfl_xor_sync(0xFFFFFFFFu, l0, s);
        l1 += __shfl_xor_sync(0xFFFFFFFFu, l1, s);
        l2 += __shfl_xor_sync(0xFFFFFFFFu, l2, s);
        l3 += __shfl_xor_sync(0xFFFFFFFFu, l3, s);
    }
    if (lane == 0) {
        s_logit[seg_l][wis * 4 + 0] = l0;
        s_logit[seg_l][wis * 4 + 1] = l1;
        s_logit[seg_l][wis * 4 + 2] = l2;
        s_logit[seg_l][wis * 4 + 3] = l3;
    }
    __syncthreads();

    // segment softmax (each warp redundantly for its own segment)
    float l = (lane < 20) ? s_logit[seg_l][lane] : -1e30f;
    float m = l;
#pragma unroll
    for (int s = 16; s > 0; s >>= 1) m = fmaxf(m, __shfl_xor_sync(0xFFFFFFFFu, m, s));
    float ev = (lane < 20) ? __expf(l - m) : 0.0f;
#pragma unroll
    for (int s = 16; s > 0; s >>= 1) ev += __shfl_xor_sync(0xFFFFFFFFu, ev, s);

    if (lane < 4) {
        float lg = s_logit[seg_l][wis * 4 + lane];
        float trans = __expf(lg - m) / ev;
        atomicAdd(&out[(size_t)eg * n_nodes + vjL], trans * att * ey);
    }
}

// ---------------------------------------------------------------------------
extern "C" void kernel_launch(void* const* d_in, const int* in_sizes, int n_in,
                              void* d_out, int out_size)
{
    const float* natt    = (const float*)d_in[0];
    const int*   edges   = (const int*)d_in[1];
    const float* edges_y = (const float*)d_in[2];
    const float* hu_in   = (const float*)d_in[3];   // [1, n_nodes, 256]
    const float* hc_in   = (const float*)d_in[4];   // [n_mem, 64]
    const float* Wc      = (const float*)d_in[5];
    const float* bc      = (const float*)d_in[6];
    const float* Wu      = (const float*)d_in[7];
    const float* bu      = (const float*)d_in[8];
    const float* rel_t   = (const float*)d_in[9];
    const float* ws      = (const float*)d_in[10];
    const float* fb      = (const float*)d_in[11];
    const float* ow      = (const float*)d_in[12];

    const int E       = in_sizes[2];
    const int n_nodes = in_sizes[3] / 256;
    const int n_mem   = in_sizes[4] / 64;
    const int n_seg   = E / 20;

    const int nb_c = (n_mem + 127) / 128;      // 1024
    const int nb_u = (n_nodes + 127) / 128;    // 391

    const int dyn_smem = (8704 + 2048) * 4;    // 43008 bytes
    cudaFuncSetAttribute(proj_both_kernel,
                         cudaFuncAttributeMaxDynamicSharedMemorySize, dyn_smem);
    cudaFuncSetAttribute(proj_both_kernel,
                         cudaFuncAttributePreferredSharedMemoryCarveout, 100);

    cudaMemsetAsync(d_out, 0, (size_t)out_size * sizeof(float));

    proj_both_kernel<<<nb_c + nb_u, 256, dyn_smem>>>(
        hc_in, Wc, bc, n_mem, nb_c, hu_in, Wu, bu, n_nodes);

    edge_kernel<<<n_seg / 2, 320>>>(natt, edges, edges_y, rel_t, ws, fb, ow,
                                    (float*)d_out, n_nodes);
}